// round 4
// baseline (speedup 1.0000x reference)
#include <cuda_runtime.h>
#include <math.h>

#define Bb 8
#define Tt 24
#define Nn 768
#define Ee 24576
#define Hh 64
#define BE 196608              // B*E
#define PRED_ELEMS (Bb*Tt*Nn)  // 147456

// ---------------- device scratch (static, no allocs) ----------------
__device__ float g_stat[4];          // mean0, mean1, rstd0, rstd1 (ddof=1)
__device__ float g_hn[Bb*Nn];
__device__ float g_sumhn[Bb];
__device__ int   g_cnt_raw[Nn];
__device__ int   g_rowptr[Nn+1];
__device__ int   g_cursor[Nn];
__device__ int   g_colidx[Ee];
__device__ int   g_cnt[Nn];          // deduped per-row counts
__device__ float g_erep[Tt*BE];      // 18.9 MB

// ---------------- prep: edge_attr mean/std (ddof=1) ----------------
__global__ void kstat(const float* __restrict__ eattr){
  __shared__ double red[1024];
  int tid = threadIdx.x;
  double s0=0,s1=0,q0=0,q1=0;
  for (int e=tid; e<Ee; e+=1024){
    double a=eattr[2*e], b=eattr[2*e+1];
    s0+=a; s1+=b; q0+=a*a; q1+=b*b;
  }
  double vals[4]={s0,s1,q0,q1};
  double out[4];
  for (int v=0; v<4; ++v){
    red[tid]=vals[v]; __syncthreads();
    for (int off=512; off; off>>=1){ if (tid<off) red[tid]+=red[tid+off]; __syncthreads(); }
    out[v]=red[0]; __syncthreads();
  }
  if (tid==0){
    double m0=out[0]/Ee, m1=out[1]/Ee;
    double v0=(out[2]-out[0]*out[0]/Ee)/(double)(Ee-1);
    double v1=(out[3]-out[1]*out[1]/Ee)/(double)(Ee-1);
    g_stat[0]=(float)m0; g_stat[1]=(float)m1;
    g_stat[2]=(float)(1.0/sqrt(v0)); g_stat[3]=(float)(1.0/sqrt(v1));
  }
  if (tid<Nn) g_cnt_raw[tid]=0;
}

__global__ void kcount(const int* __restrict__ eidx){
  int e = blockIdx.x*256+threadIdx.x;
  if (e<Ee) atomicAdd(&g_cnt_raw[eidx[Ee+e]],1);
}

__global__ void kscan(){
  __shared__ int a[Nn];
  int t=threadIdx.x;
  if (t<Nn) a[t]=g_cnt_raw[t];
  __syncthreads();
  for (int d=1; d<Nn; d<<=1){
    int v=0;
    if (t<Nn && t>=d) v=a[t-d];
    __syncthreads();
    if (t<Nn) a[t]+=v;
    __syncthreads();
  }
  if (t<Nn){ g_rowptr[t+1]=a[t]; g_cursor[t]=a[t]-g_cnt_raw[t]; }
  if (t==0) g_rowptr[0]=0;
}

__global__ void kfill(const int* __restrict__ eidx){
  int e = blockIdx.x*256+threadIdx.x;
  if (e<Ee){ int pos=atomicAdd(&g_cursor[eidx[Ee+e]],1); g_colidx[pos]=e; }
}

// canonicalize: sort each row by edge id (deterministic regardless of atomic
// order), then dedup by src keeping the LAST edge (sequential .set semantics)
__global__ void kfix(const int* __restrict__ eidx){
  int t = blockIdx.x*256+threadIdx.x;
  if (t>=Nn) return;
  int rs=g_rowptr[t], re=g_rowptr[t+1];
  for (int i=rs+1;i<re;i++){
    int key=g_colidx[i]; int j=i-1;
    while(j>=rs && g_colidx[j]>key){ g_colidx[j+1]=g_colidx[j]; j--; }
    g_colidx[j+1]=key;
  }
  int w=rs;
  for (int i=rs;i<re;i++){
    int e=g_colidx[i]; int src=eidx[e];
    bool later=false;
    for (int j2=i+1;j2<re;j2++){ if (eidx[g_colidx[j2]]==src){later=true;break;} }
    if (!later) g_colidx[w++]=e;
  }
  g_cnt[t]=w-rs;
}

__global__ void khn(const float* __restrict__ pm25,
                    const float* __restrict__ Wn, const float* __restrict__ bn){
  __shared__ float red[256];
  int b=blockIdx.x, t=threadIdx.x;
  float w=Wn[0], bb=bn[0];
  float s=0.f;
  for (int n=t;n<Nn;n+=256){ float h=pm25[b*Nn+n]*w+bb; g_hn[b*Nn+n]=h; s+=h; }
  red[t]=s; __syncthreads();
  for(int off=128;off;off>>=1){ if(t<off) red[t]+=red[t+off]; __syncthreads(); }
  if(t==0) g_sumhn[b]=red[0];
}

// ---------------- main GRU + MLP: 64 rows/block, h resident in SMEM, all 24 steps ----------------
__global__ void __launch_bounds__(256,2) kgru(
    const float* __restrict__ feature, const int* __restrict__ eidx,
    const float* __restrict__ eattr,   const float* __restrict__ wmean,
    const float* __restrict__ wstd,    const float* __restrict__ W_ih,
    const float* __restrict__ W_hh,    const float* __restrict__ b_ih,
    const float* __restrict__ b_hh,    const float* __restrict__ W1,
    const float* __restrict__ b1,      const float* __restrict__ W2,
    const float* __restrict__ b2)
{
  extern __shared__ float sm[];
  float* sW  = sm;            // 64x192 W_hh (k-major)
  float* sW1v= sW + 12288;    // 64x64
  float* sh  = sW1v + 4096;   // 64 rows x 64
  float* sWih= sh + 4096;     // 3x192
  float* sbih= sWih+576;      // 192
  float* sbhh= sbih+192;      // 192
  float* sb1 = sbhh+192;      // 64
  float* sW2v= sb1+64;        // 64
  float* sEA0= sW2v+64;       // 64
  float* sEA1= sEA0+64;       // 64
  float* sDIR= sEA1+64;       // 64
  float* sC3D= sDIR+64;       // 64
  float* sEW = sC3D+64;       // 64
  int*   sSRC= (int*)(sEW+64);// 64

  const int tid  = threadIdx.x;
  const int base = blockIdx.x*64;   // global row base; 64 | E so batch is constant per block
  const int bIdx = base / Ee;
  const int e0   = base % Ee;

  for (int i=tid;i<3072;i+=256) ((float4*)sW)[i]   = ((const float4*)W_hh)[i];
  for (int i=tid;i<1024;i+=256) ((float4*)sW1v)[i] = ((const float4*)W1)[i];
  for (int i=tid;i<576;i+=256) sWih[i]=W_ih[i];
  for (int i=tid;i<192;i+=256){ sbih[i]=b_ih[i]; sbhh[i]=b_hh[i]; }
  if (tid<64){ sb1[tid]=b1[tid]; sW2v[tid]=W2[tid]; }
  if (tid<64){
    int e=e0+tid;
    sSRC[tid]=eidx[e];
    float dd=eattr[2*e], dr=eattr[2*e+1];
    sDIR[tid]=dr;
    sC3D[tid]=3.f/dd;
    sEA0[tid]=(dd-g_stat[0])*g_stat[2];
    sEA1[tid]=(dr-g_stat[1])*g_stat[3];
  }
  for (int i=tid;i<4096;i+=256) sh[i]=0.f;   // en0 = zeros
  const float wm0=wmean[0], wm1=wmean[1], ws0=wstd[0], ws1=wstd[1];
  const float b2v=b2[0];
  __syncthreads();

  const int jq = tid & 15;   // 16 j-quartets
  const int rq = tid >> 4;   // 16 row-quartets
  const int j0 = jq*4;
  const int r0 = rq*4;

  for (int t=0;t<Tt;t++){
    // --- edge weight for this step ---
    if (tid<64){
      const float* fp = feature + (((bIdx*25)+1+t)*Nn + sSRC[tid])*4 + 2;
      float speed = fp[0]*ws0+wm0;
      float wdir  = fp[1]*ws1+wm1;
      float ew = sC3D[tid]*speed*cosf(sDIR[tid]-wdir);
      sEW[tid] = fmaxf(ew,0.f);
    }
    __syncthreads();

    // --- gh = h @ W_hh : each thread accumulates 4 rows x 4 j x 3 gates ---
    float aR[4][4], aZ[4][4], aN[4][4];
    #pragma unroll
    for(int i=0;i<4;i++)
      #pragma unroll
      for(int l=0;l<4;l++){aR[i][l]=0.f;aZ[i][l]=0.f;aN[i][l]=0.f;}

    #pragma unroll 4
    for (int k4=0;k4<16;k4++){
      float4 h4[4];
      #pragma unroll
      for(int i=0;i<4;i++) h4[i]=*(const float4*)&sh[(r0+i)*64+k4*4];
      #pragma unroll
      for(int kk=0;kk<4;kk++){
        const float* wrow = &sW[(k4*4+kk)*192];
        float4 wr = *(const float4*)&wrow[j0];
        float4 wz = *(const float4*)&wrow[64+j0];
        float4 wn = *(const float4*)&wrow[128+j0];
        #pragma unroll
        for(int i=0;i<4;i++){
          float hv = (kk==0)?h4[i].x:(kk==1)?h4[i].y:(kk==2)?h4[i].z:h4[i].w;
          aR[i][0]+=hv*wr.x; aR[i][1]+=hv*wr.y; aR[i][2]+=hv*wr.z; aR[i][3]+=hv*wr.w;
          aZ[i][0]+=hv*wz.x; aZ[i][1]+=hv*wz.y; aZ[i][2]+=hv*wz.z; aZ[i][3]+=hv*wz.w;
          aN[i][0]+=hv*wn.x; aN[i][1]+=hv*wn.y; aN[i][2]+=hv*wn.z; aN[i][3]+=hv*wn.w;
        }
      }
    }

    // --- gates + state update ---
    float hnew[4][4];
    #pragma unroll
    for(int i=0;i<4;i++){
      const int r=r0+i;
      const float ea0=sEA0[r], ea1=sEA1[r], ew=sEW[r];
      #pragma unroll
      for(int l=0;l<4;l++){
        const int j=j0+l;
        float giR = ea0*sWih[j]     + ea1*sWih[192+j] + ew*sWih[384+j] + sbih[j];
        float giZ = ea0*sWih[64+j]  + ea1*sWih[256+j] + ew*sWih[448+j] + sbih[64+j];
        float giN = ea0*sWih[128+j] + ea1*sWih[320+j] + ew*sWih[512+j] + sbih[128+j];
        float rg = __fdividef(1.f, 1.f+__expf(-(giR+aR[i][l]+sbhh[j])));
        float zg = __fdividef(1.f, 1.f+__expf(-(giZ+aZ[i][l]+sbhh[64+j])));
        float pre = giN + rg*(aN[i][l]+sbhh[128+j]);
        float nn = 1.f - __fdividef(2.f, __expf(2.f*pre)+1.f);   // tanh(pre), sat-safe
        float ho = sh[r*64+j];
        hnew[i][l] = nn + zg*(ho-nn);
      }
    }
    __syncthreads();
    #pragma unroll
    for(int i=0;i<4;i++){
      float4 hv = make_float4(hnew[i][0],hnew[i][1],hnew[i][2],hnew[i][3]);
      *(float4*)&sh[(r0+i)*64+j0] = hv;
    }
    __syncthreads();

    // --- e_rep = relu(h_new @ W1 + b1) @ W2 + b2 ---
    float am[4][4];
    #pragma unroll
    for(int i=0;i<4;i++)
      #pragma unroll
      for(int l=0;l<4;l++) am[i][l]=0.f;
    #pragma unroll 4
    for (int k4=0;k4<16;k4++){
      float4 h4[4];
      #pragma unroll
      for(int i=0;i<4;i++) h4[i]=*(const float4*)&sh[(r0+i)*64+k4*4];
      #pragma unroll
      for(int kk=0;kk<4;kk++){
        float4 w1v = *(const float4*)&sW1v[(k4*4+kk)*64+j0];
        #pragma unroll
        for(int i=0;i<4;i++){
          float hv = (kk==0)?h4[i].x:(kk==1)?h4[i].y:(kk==2)?h4[i].z:h4[i].w;
          am[i][0]+=hv*w1v.x; am[i][1]+=hv*w1v.y; am[i][2]+=hv*w1v.z; am[i][3]+=hv*w1v.w;
        }
      }
    }
    float p[4];
    #pragma unroll
    for(int i=0;i<4;i++){
      float s=0.f;
      #pragma unroll
      for(int l=0;l<4;l++){
        float a=fmaxf(am[i][l]+sb1[j0+l],0.f);
        s += a*sW2v[j0+l];
      }
      p[i]=s;
    }
    #pragma unroll
    for(int off=8;off;off>>=1){
      #pragma unroll
      for(int i=0;i<4;i++) p[i]+=__shfl_down_sync(0xffffffffu,p[i],off,16);
    }
    if (jq==0){
      #pragma unroll
      for(int i=0;i<4;i++) g_erep[t*BE + base + r0 + i] = p[i]+b2v;
    }
    __syncthreads();
  }
}

// ---------------- softmax rows of R + c_pred, streamed dense writes ----------------
__global__ void krow(const int* __restrict__ eidx, float* __restrict__ out)
{
  __shared__ float srow[8][Nn];
  const int wid = threadIdx.x>>5, lane=threadIdx.x&31;
  const int gid = blockIdx.x*8 + wid;     // == (b*Tt+t)*Nn + tgt
  const int tgt = gid % Nn;
  const int bt  = gid / Nn;
  const int t   = bt % Tt;
  const int b   = bt / Tt;
  const int rs  = g_rowptr[tgt];
  const int cnt = g_cnt[tgt];
  const float* er  = g_erep + (size_t)t*BE + (size_t)b*Ee;
  const float* hnb = g_hn + b*Nn;

  float vmax=0.f;  // empty slots contribute 0
  for (int i=lane;i<cnt;i+=32){ float v=er[g_colidx[rs+i]]; vmax=fmaxf(vmax,v); }
  #pragma unroll
  for(int off=16;off;off>>=1) vmax=fmaxf(vmax,__shfl_xor_sync(0xffffffffu,vmax,off));

  float se=0.f, shw=0.f, shf=0.f;
  for (int i=lane;i<cnt;i+=32){
    int e=g_colidx[rs+i];
    float v=er[e];
    float ex=__expf(v-vmax);
    float hv=hnb[eidx[e]];
    se+=ex; shw+=ex*hv; shf+=hv;
  }
  #pragma unroll
  for(int off=16;off;off>>=1){
    se +=__shfl_xor_sync(0xffffffffu,se ,off);
    shw+=__shfl_xor_sync(0xffffffffu,shw,off);
    shf+=__shfl_xor_sync(0xffffffffu,shf,off);
  }
  float ez  = __expf(-vmax);
  float inv = __fdividef(1.f, (float)(Nn-cnt)*ez + se);
  float defv= ez*inv;
  if (lane==0) out[gid] = (ez*(g_sumhn[b]-shf)+shw)*inv;   // c_pred

  float* row = srow[wid];
  for (int s=lane;s<Nn;s+=32) row[s]=defv;
  __syncwarp();
  for (int i=lane;i<cnt;i+=32){
    int e=g_colidx[rs+i];
    row[eidx[e]] = __expf(er[e]-vmax)*inv;
  }
  __syncwarp();
  float* dst = out + PRED_ELEMS + (size_t)gid*Nn;
  float4* d4=(float4*)dst; const float4* s4=(const float4*)row;
  for (int s=lane;s<Nn/4;s+=32) d4[s]=s4[s];
}

// ---------------- launch ----------------
extern "C" void kernel_launch(void* const* d_in, const int* in_sizes, int n_in,
                              void* d_out, int out_size){
  const float* pm25   =(const float*)d_in[0];
  const float* feature=(const float*)d_in[1];
  const int*   eidx   =(const int*)  d_in[2];
  const float* eattr  =(const float*)d_in[3];
  const float* wmean  =(const float*)d_in[4];
  const float* wstd   =(const float*)d_in[5];
  const float* W_ih   =(const float*)d_in[6];
  const float* W_hh   =(const float*)d_in[7];
  const float* b_ih   =(const float*)d_in[8];
  const float* b_hh   =(const float*)d_in[9];
  const float* W1     =(const float*)d_in[10];
  const float* b1     =(const float*)d_in[11];
  const float* W2     =(const float*)d_in[12];
  const float* b2     =(const float*)d_in[13];
  const float* W_node =(const float*)d_in[14];
  const float* b_node =(const float*)d_in[15];
  float* out=(float*)d_out;

  const int smem_bytes = 21888*4 + 64*4;   // 87808
  cudaFuncSetAttribute(kgru, cudaFuncAttributeMaxDynamicSharedMemorySize, smem_bytes);

  kstat <<<1,1024>>>(eattr);
  kcount<<<96,256>>>(eidx);
  kscan <<<1,1024>>>();
  kfill <<<96,256>>>(eidx);
  kfix  <<<3,256>>>(eidx);
  khn   <<<8,256>>>(pm25,W_node,b_node);
  kgru  <<<3072,256,smem_bytes>>>(feature,eidx,eattr,wmean,wstd,
                                  W_ih,W_hh,b_ih,b_hh,W1,b1,W2,b2);
  krow  <<<18432,256>>>(eidx,out);
}